// round 1
// baseline (speedup 1.0000x reference)
#include <cuda_runtime.h>
#include <stdint.h>

// Problem constants
#define BATCH 8192
#define HDIM  1024
#define KTOT  2048      // per-gate K (x-half + h-half)

// GEMM tiling
#define BM 128
#define BN 128
#define BK 32
#define SPAD 36         // smem row pitch in floats: (36*g + r) % 32 distinct -> conflict-free
#define KTILES (KTOT / BK)   // 64

// Preactivation scratch: 4 gates x B x H fp32 = 134 MB (device global, allowed)
__device__ float g_pre[4ull * BATCH * HDIM];

__device__ __forceinline__ uint32_t f2tf32(float a) {
    uint32_t r;
    asm("cvt.rna.tf32.f32 %0, %1;" : "=r"(r) : "f"(a));
    return r;
}

__device__ __forceinline__ void mma8(float* d, const uint32_t* a, const uint32_t* b) {
    asm volatile(
        "mma.sync.aligned.m16n8k8.row.col.f32.tf32.tf32.f32 "
        "{%0,%1,%2,%3}, {%4,%5,%6,%7}, {%8,%9}, {%0,%1,%2,%3};"
        : "+f"(d[0]), "+f"(d[1]), "+f"(d[2]), "+f"(d[3])
        : "r"(a[0]), "r"(a[1]), "r"(a[2]), "r"(a[3]), "r"(b[0]), "r"(b[1]));
}

// Fused masked-input GEMM: for gate g, P_g = [x.*m_gx | u.*m_gh] @ [Wx_g ; Wh_g]^T + b_g
// u = hx for gates f,i,o ; u = x for gate c (faithful to reference quirk).
__global__ void __launch_bounds__(256, 1)
lstm_gemm(const float* __restrict__ x,  const float* __restrict__ hx,
          const float* __restrict__ mask_x, const float* __restrict__ mask_h,
          const float* __restrict__ Wxf, const float* __restrict__ Wxi,
          const float* __restrict__ Wxo, const float* __restrict__ Wxc,
          const float* __restrict__ Whf, const float* __restrict__ Whi,
          const float* __restrict__ Who, const float* __restrict__ Whc,
          const float* __restrict__ bf,  const float* __restrict__ bi,
          const float* __restrict__ bo,  const float* __restrict__ bc)
{
    extern __shared__ float sm[];
    float* As = sm;                       // [2][BM][SPAD]
    float* Bs = sm + 2 * BM * SPAD;       // [2][BN][SPAD]

    const int g  = blockIdx.z;            // 0=f 1=i 2=o 3=c
    const int nb = blockIdx.x * BN;       // n fastest -> x/mask L2 reuse across n-tiles
    const int mb = blockIdx.y * BM;
    const int tid  = threadIdx.x;
    const int lane = tid & 31;
    const int wid  = tid >> 5;
    const int wm   = wid & 3;             // warp grid 4(M) x 2(N)
    const int wn   = wid >> 2;

    const float* Wxg = (g == 0) ? Wxf : (g == 1) ? Wxi : (g == 2) ? Wxo : Wxc;
    const float* Whg = (g == 0) ? Whf : (g == 1) ? Whi : (g == 2) ? Who : Whc;
    const float* bg  = (g == 0) ? bf  : (g == 1) ? bi  : (g == 2) ? bo  : bc;
    const float* u   = (g == 3) ? x : hx;
    const int moff = g * HDIM;            // mask column offset (split order f,i,o,c)

    // staging map: 128 rows x 8 float4/row, 256 threads -> 4 float4 each
    const int srow = tid >> 3;            // 0..31, +p*32
    const int scol = (tid & 7) * 4;       // 0..28

    float4 xr[4], mr[4], wr[4];

    float acc[2][8][4];
#pragma unroll
    for (int a = 0; a < 2; a++)
#pragma unroll
        for (int j = 0; j < 8; j++)
#pragma unroll
            for (int q = 0; q < 4; q++) acc[a][j][q] = 0.f;

    auto LOAD = [&](int it) {
        const int kt = it * BK;
        const float* src; const float* msk; const float* wsrc; int kk;
        if (kt < HDIM) { src = x; msk = mask_x; wsrc = Wxg; kk = kt; }
        else           { src = u; msk = mask_h; wsrc = Whg; kk = kt - HDIM; }
#pragma unroll
        for (int p = 0; p < 4; p++) {
            const int r = srow + p * 32;
            xr[p] = *(const float4*)(src  + (size_t)(mb + r) * HDIM     + kk + scol);
            mr[p] = *(const float4*)(msk  + (size_t)(mb + r) * (4*HDIM) + moff + kk + scol);
            wr[p] = *(const float4*)(wsrc + (size_t)(nb + r) * HDIM     + kk + scol);
        }
    };

    auto STORE = [&](int buf) {
        float* a = As + buf * BM * SPAD;
        float* b = Bs + buf * BN * SPAD;
#pragma unroll
        for (int p = 0; p < 4; p++) {
            const int r = srow + p * 32;
            float4 av;
            av.x = __uint_as_float(f2tf32(xr[p].x * mr[p].x));
            av.y = __uint_as_float(f2tf32(xr[p].y * mr[p].y));
            av.z = __uint_as_float(f2tf32(xr[p].z * mr[p].z));
            av.w = __uint_as_float(f2tf32(xr[p].w * mr[p].w));
            *(float4*)(a + r * SPAD + scol) = av;
            float4 bv;
            bv.x = __uint_as_float(f2tf32(wr[p].x));
            bv.y = __uint_as_float(f2tf32(wr[p].y));
            bv.z = __uint_as_float(f2tf32(wr[p].z));
            bv.w = __uint_as_float(f2tf32(wr[p].w));
            *(float4*)(b + r * SPAD + scol) = bv;
        }
    };

    const int gi = lane >> 2;   // groupID
    const int ti = lane & 3;    // thread-in-group

    auto COMPUTE = [&](int buf) {
        const float* a = As + buf * BM * SPAD;
        const float* b = Bs + buf * BN * SPAD;
#pragma unroll
        for (int ks = 0; ks < 4; ks++) {
            const int kb = ks * 8;
            uint32_t af[2][4];
#pragma unroll
            for (int mi = 0; mi < 2; mi++) {
                const float* ap = a + (wm * 32 + mi * 16 + gi) * SPAD + kb + ti;
                af[mi][0] = __float_as_uint(ap[0]);
                af[mi][1] = __float_as_uint(ap[8 * SPAD]);
                af[mi][2] = __float_as_uint(ap[4]);
                af[mi][3] = __float_as_uint(ap[8 * SPAD + 4]);
            }
#pragma unroll
            for (int j = 0; j < 8; j++) {
                const float* bp = b + (wn * 64 + j * 8 + gi) * SPAD + kb + ti;
                uint32_t bfr[2] = { __float_as_uint(bp[0]), __float_as_uint(bp[4]) };
#pragma unroll
                for (int mi = 0; mi < 2; mi++) mma8(acc[mi][j], af[mi], bfr);
            }
        }
    };

    // pipelined mainloop: reg prefetch + double-buffered smem, 1 barrier/iter
    LOAD(0);
    STORE(0);
    __syncthreads();
#pragma unroll 1
    for (int it = 0; it < KTILES; it++) {
        if (it + 1 < KTILES) LOAD(it + 1);
        COMPUTE(it & 1);
        if (it + 1 < KTILES) STORE((it + 1) & 1);
        __syncthreads();
    }

    // epilogue: add bias, write preactivation scratch
    float* pre = g_pre + (size_t)g * BATCH * HDIM;
#pragma unroll
    for (int mi = 0; mi < 2; mi++) {
#pragma unroll
        for (int j = 0; j < 8; j++) {
            const int col  = nb + wn * 64 + j * 8 + ti * 2;
            const float2 bb = *(const float2*)(bg + col);
            const int row0 = mb + wm * 32 + mi * 16 + gi;
            float2 v0 = { acc[mi][j][0] + bb.x, acc[mi][j][1] + bb.y };
            float2 v1 = { acc[mi][j][2] + bb.x, acc[mi][j][3] + bb.y };
            *(float2*)(pre + (size_t)row0 * HDIM + col)       = v0;
            *(float2*)(pre + (size_t)(row0 + 8) * HDIM + col) = v1;
        }
    }
}

__device__ __forceinline__ float sigmoidf_(float v) { return 1.0f / (1.0f + expf(-v)); }

// Elementwise gate fusion: reads 4 preacts + cx, writes [hx_new ; cx_new]
__global__ void __launch_bounds__(256)
lstm_gate(const float* __restrict__ cx, float* __restrict__ out)
{
    const size_t BH = (size_t)BATCH * HDIM;
    const size_t i = ((size_t)blockIdx.x * blockDim.x + threadIdx.x) * 4;
    if (i >= BH) return;

    float4 pf = *(const float4*)(g_pre + i);
    float4 pi = *(const float4*)(g_pre + BH + i);
    float4 po = *(const float4*)(g_pre + 2 * BH + i);
    float4 pc = *(const float4*)(g_pre + 3 * BH + i);
    float4 cv = *(const float4*)(cx + i);

    float fv[4] = { pf.x, pf.y, pf.z, pf.w };
    float iv[4] = { pi.x, pi.y, pi.z, pi.w };
    float ov[4] = { po.x, po.y, po.z, po.w };
    float cc[4] = { pc.x, pc.y, pc.z, pc.w };
    float cxv[4] = { cv.x, cv.y, cv.z, cv.w };
    float hn[4], cn[4];
#pragma unroll
    for (int q = 0; q < 4; q++) {
        float fg = sigmoidf_(fv[q]);
        float ig = sigmoidf_(iv[q]);
        float og = sigmoidf_(ov[q]);
        float ct = tanhf(cc[q]);
        float c2 = fg * cxv[q] + ig * ct;
        cn[q] = c2;
        hn[q] = og * tanhf(c2);
    }
    float4 h4 = { hn[0], hn[1], hn[2], hn[3] };
    float4 c4 = { cn[0], cn[1], cn[2], cn[3] };
    *(float4*)(out + i)      = h4;
    *(float4*)(out + BH + i) = c4;
}

extern "C" void kernel_launch(void* const* d_in, const int* in_sizes, int n_in,
                              void* d_out, int out_size)
{
    const float* x      = (const float*)d_in[0];
    const float* hx     = (const float*)d_in[1];
    const float* cx     = (const float*)d_in[2];
    const float* mask_x = (const float*)d_in[3];
    const float* mask_h = (const float*)d_in[4];
    const float* Wx_i   = (const float*)d_in[5];
    const float* Wx_f   = (const float*)d_in[6];
    const float* Wx_c   = (const float*)d_in[7];
    const float* Wx_o   = (const float*)d_in[8];
    const float* Wh_i   = (const float*)d_in[9];
    const float* Wh_f   = (const float*)d_in[10];
    const float* Wh_c   = (const float*)d_in[11];
    const float* Wh_o   = (const float*)d_in[12];
    const float* bx_i   = (const float*)d_in[13];
    const float* bx_f   = (const float*)d_in[14];
    const float* bx_c   = (const float*)d_in[15];
    const float* bx_o   = (const float*)d_in[16];

    const int smem_bytes = 2 * (BM + BN) * SPAD * sizeof(float);  // 73728
    cudaFuncSetAttribute(lstm_gemm, cudaFuncAttributeMaxDynamicSharedMemorySize, smem_bytes);

    dim3 grid(HDIM / BN, BATCH / BM, 4);   // (8, 64, 4)
    lstm_gemm<<<grid, 256, smem_bytes>>>(
        x, hx, mask_x, mask_h,
        Wx_f, Wx_i, Wx_o, Wx_c,
        Wh_f, Wh_i, Wh_o, Wh_c,
        bx_f, bx_i, bx_o, bx_c);

    const size_t BH = (size_t)BATCH * HDIM;
    lstm_gate<<<(unsigned)(BH / 4 / 256), 256>>>(cx, (float*)d_out);
}

// round 2
// speedup vs baseline: 1.0033x; 1.0033x over previous
#include <cuda_runtime.h>
#include <stdint.h>

// Problem constants
#define BATCH 8192
#define HDIM  1024
#define KTOT  2048      // per-gate K (x-half + h-half)

// GEMM tiling
#define BM 128
#define BN 128
#define BK 32
#define SPAD 36         // smem row pitch in floats: (36*g + r) % 32 distinct -> conflict-free
#define KTILES (KTOT / BK)   // 64

// Preactivation scratch: 4 gates x B x H fp32 = 134 MB (device global, allowed)
__device__ float g_pre[4ull * BATCH * HDIM];

__device__ __forceinline__ uint32_t f2tf32(float a) {
    uint32_t r;
    asm("cvt.rna.tf32.f32 %0, %1;" : "=r"(r) : "f"(a));
    return r;
}

__device__ __forceinline__ void mma8(float* d, const uint32_t* a, const uint32_t* b) {
    asm volatile(
        "mma.sync.aligned.m16n8k8.row.col.f32.tf32.tf32.f32 "
        "{%0,%1,%2,%3}, {%4,%5,%6,%7}, {%8,%9}, {%0,%1,%2,%3};"
        : "+f"(d[0]), "+f"(d[1]), "+f"(d[2]), "+f"(d[3])
        : "r"(a[0]), "r"(a[1]), "r"(a[2]), "r"(a[3]), "r"(b[0]), "r"(b[1]));
}

// Fused masked-input GEMM: for gate g, P_g = [x.*m_gx | u.*m_gh] @ [Wx_g ; Wh_g]^T + b_g
// u = hx for gates f,i,o ; u = x for gate c (faithful to reference quirk).
__global__ void __launch_bounds__(256, 1)
lstm_gemm(const float* __restrict__ x,  const float* __restrict__ hx,
          const float* __restrict__ mask_x, const float* __restrict__ mask_h,
          const float* __restrict__ Wxf, const float* __restrict__ Wxi,
          const float* __restrict__ Wxo, const float* __restrict__ Wxc,
          const float* __restrict__ Whf, const float* __restrict__ Whi,
          const float* __restrict__ Who, const float* __restrict__ Whc,
          const float* __restrict__ bf,  const float* __restrict__ bi,
          const float* __restrict__ bo,  const float* __restrict__ bc)
{
    extern __shared__ float sm[];
    float* As = sm;                       // [2][BM][SPAD]
    float* Bs = sm + 2 * BM * SPAD;       // [2][BN][SPAD]

    const int g  = blockIdx.z;            // 0=f 1=i 2=o 3=c
    const int nb = blockIdx.x * BN;       // n fastest -> x/mask L2 reuse across n-tiles
    const int mb = blockIdx.y * BM;
    const int tid  = threadIdx.x;
    const int lane = tid & 31;
    const int wid  = tid >> 5;
    const int wm   = wid & 3;             // warp grid 4(M) x 2(N)
    const int wn   = wid >> 2;

    const float* Wxg = (g == 0) ? Wxf : (g == 1) ? Wxi : (g == 2) ? Wxo : Wxc;
    const float* Whg = (g == 0) ? Whf : (g == 1) ? Whi : (g == 2) ? Who : Whc;
    const float* bg  = (g == 0) ? bf  : (g == 1) ? bi  : (g == 2) ? bo  : bc;
    const float* u   = (g == 3) ? x : hx;
    const int moff = g * HDIM;            // mask column offset (split order f,i,o,c)

    // staging map: 128 rows x 8 float4/row, 256 threads -> 4 float4 each
    const int srow = tid >> 3;            // 0..31, +p*32
    const int scol = (tid & 7) * 4;       // 0..28

    float4 xr[4], mr[4], wr[4];

    float acc[2][8][4];
#pragma unroll
    for (int a = 0; a < 2; a++)
#pragma unroll
        for (int j = 0; j < 8; j++)
#pragma unroll
            for (int q = 0; q < 4; q++) acc[a][j][q] = 0.f;

    auto LOAD = [&](int it) {
        const int kt = it * BK;
        const float* src; const float* msk; const float* wsrc; int kk;
        if (kt < HDIM) { src = x; msk = mask_x; wsrc = Wxg; kk = kt; }
        else           { src = u; msk = mask_h; wsrc = Whg; kk = kt - HDIM; }
#pragma unroll
        for (int p = 0; p < 4; p++) {
            const int r = srow + p * 32;
            xr[p] = *(const float4*)(src  + (size_t)(mb + r) * HDIM     + kk + scol);
            mr[p] = *(const float4*)(msk  + (size_t)(mb + r) * (4*HDIM) + moff + kk + scol);
            wr[p] = *(const float4*)(wsrc + (size_t)(nb + r) * HDIM     + kk + scol);
        }
    };

    auto STORE = [&](int buf) {
        float* a = As + buf * BM * SPAD;
        float* b = Bs + buf * BN * SPAD;
#pragma unroll
        for (int p = 0; p < 4; p++) {
            const int r = srow + p * 32;
            float4 av;
            av.x = __uint_as_float(f2tf32(xr[p].x * mr[p].x));
            av.y = __uint_as_float(f2tf32(xr[p].y * mr[p].y));
            av.z = __uint_as_float(f2tf32(xr[p].z * mr[p].z));
            av.w = __uint_as_float(f2tf32(xr[p].w * mr[p].w));
            *(float4*)(a + r * SPAD + scol) = av;
            float4 bv;
            bv.x = __uint_as_float(f2tf32(wr[p].x));
            bv.y = __uint_as_float(f2tf32(wr[p].y));
            bv.z = __uint_as_float(f2tf32(wr[p].z));
            bv.w = __uint_as_float(f2tf32(wr[p].w));
            *(float4*)(b + r * SPAD + scol) = bv;
        }
    };

    const int gi = lane >> 2;   // groupID
    const int ti = lane & 3;    // thread-in-group

    auto COMPUTE = [&](int buf) {
        const float* a = As + buf * BM * SPAD;
        const float* b = Bs + buf * BN * SPAD;
#pragma unroll
        for (int ks = 0; ks < 4; ks++) {
            const int kb = ks * 8;
            uint32_t af[2][4];
#pragma unroll
            for (int mi = 0; mi < 2; mi++) {
                const float* ap = a + (wm * 32 + mi * 16 + gi) * SPAD + kb + ti;
                af[mi][0] = __float_as_uint(ap[0]);
                af[mi][1] = __float_as_uint(ap[8 * SPAD]);
                af[mi][2] = __float_as_uint(ap[4]);
                af[mi][3] = __float_as_uint(ap[8 * SPAD + 4]);
            }
#pragma unroll
            for (int j = 0; j < 8; j++) {
                const float* bp = b + (wn * 64 + j * 8 + gi) * SPAD + kb + ti;
                uint32_t bfr[2] = { __float_as_uint(bp[0]), __float_as_uint(bp[4]) };
#pragma unroll
                for (int mi = 0; mi < 2; mi++) mma8(acc[mi][j], af[mi], bfr);
            }
        }
    };

    // pipelined mainloop: reg prefetch + double-buffered smem, 1 barrier/iter
    LOAD(0);
    STORE(0);
    __syncthreads();
#pragma unroll 1
    for (int it = 0; it < KTILES; it++) {
        if (it + 1 < KTILES) LOAD(it + 1);
        COMPUTE(it & 1);
        if (it + 1 < KTILES) STORE((it + 1) & 1);
        __syncthreads();
    }

    // epilogue: add bias, write preactivation scratch
    float* pre = g_pre + (size_t)g * BATCH * HDIM;
#pragma unroll
    for (int mi = 0; mi < 2; mi++) {
#pragma unroll
        for (int j = 0; j < 8; j++) {
            const int col  = nb + wn * 64 + j * 8 + ti * 2;
            const float2 bb = *(const float2*)(bg + col);
            const int row0 = mb + wm * 32 + mi * 16 + gi;
            float2 v0 = { acc[mi][j][0] + bb.x, acc[mi][j][1] + bb.y };
            float2 v1 = { acc[mi][j][2] + bb.x, acc[mi][j][3] + bb.y };
            *(float2*)(pre + (size_t)row0 * HDIM + col)       = v0;
            *(float2*)(pre + (size_t)(row0 + 8) * HDIM + col) = v1;
        }
    }
}

__device__ __forceinline__ float sigmoidf_(float v) { return 1.0f / (1.0f + expf(-v)); }

// Elementwise gate fusion: reads 4 preacts + cx, writes [hx_new ; cx_new]
__global__ void __launch_bounds__(256)
lstm_gate(const float* __restrict__ cx, float* __restrict__ out)
{
    const size_t BH = (size_t)BATCH * HDIM;
    const size_t i = ((size_t)blockIdx.x * blockDim.x + threadIdx.x) * 4;
    if (i >= BH) return;

    float4 pf = *(const float4*)(g_pre + i);
    float4 pi = *(const float4*)(g_pre + BH + i);
    float4 po = *(const float4*)(g_pre + 2 * BH + i);
    float4 pc = *(const float4*)(g_pre + 3 * BH + i);
    float4 cv = *(const float4*)(cx + i);

    float fv[4] = { pf.x, pf.y, pf.z, pf.w };
    float iv[4] = { pi.x, pi.y, pi.z, pi.w };
    float ov[4] = { po.x, po.y, po.z, po.w };
    float cc[4] = { pc.x, pc.y, pc.z, pc.w };
    float cxv[4] = { cv.x, cv.y, cv.z, cv.w };
    float hn[4], cn[4];
#pragma unroll
    for (int q = 0; q < 4; q++) {
        float fg = sigmoidf_(fv[q]);
        float ig = sigmoidf_(iv[q]);
        float og = sigmoidf_(ov[q]);
        float ct = tanhf(cc[q]);
        float c2 = fg * cxv[q] + ig * ct;
        cn[q] = c2;
        hn[q] = og * tanhf(c2);
    }
    float4 h4 = { hn[0], hn[1], hn[2], hn[3] };
    float4 c4 = { cn[0], cn[1], cn[2], cn[3] };
    *(float4*)(out + i)      = h4;
    *(float4*)(out + BH + i) = c4;
}

extern "C" void kernel_launch(void* const* d_in, const int* in_sizes, int n_in,
                              void* d_out, int out_size)
{
    const float* x      = (const float*)d_in[0];
    const float* hx     = (const float*)d_in[1];
    const float* cx     = (const float*)d_in[2];
    const float* mask_x = (const float*)d_in[3];
    const float* mask_h = (const float*)d_in[4];
    const float* Wx_i   = (const float*)d_in[5];
    const float* Wx_f   = (const float*)d_in[6];
    const float* Wx_c   = (const float*)d_in[7];
    const float* Wx_o   = (const float*)d_in[8];
    const float* Wh_i   = (const float*)d_in[9];
    const float* Wh_f   = (const float*)d_in[10];
    const float* Wh_c   = (const float*)d_in[11];
    const float* Wh_o   = (const float*)d_in[12];
    const float* bx_i   = (const float*)d_in[13];
    const float* bx_f   = (const float*)d_in[14];
    const float* bx_c   = (const float*)d_in[15];
    const float* bx_o   = (const float*)d_in[16];

    const int smem_bytes = 2 * (BM + BN) * SPAD * sizeof(float);  // 73728
    cudaFuncSetAttribute(lstm_gemm, cudaFuncAttributeMaxDynamicSharedMemorySize, smem_bytes);

    dim3 grid(HDIM / BN, BATCH / BM, 4);   // (8, 64, 4)
    lstm_gemm<<<grid, 256, smem_bytes>>>(
        x, hx, mask_x, mask_h,
        Wx_f, Wx_i, Wx_o, Wx_c,
        Wh_f, Wh_i, Wh_o, Wh_c,
        bx_f, bx_i, bx_o, bx_c);

    const size_t BH = (size_t)BATCH * HDIM;
    lstm_gate<<<(unsigned)(BH / 4 / 256), 256>>>(cx, (float*)d_out);
}